// round 1
// baseline (speedup 1.0000x reference)
#include <cuda_runtime.h>
#include <cstddef>

#define TPB 256

// Parameter block: 342 floats, layout matches pack order exactly.
struct Params {
    float mW0[8][2]; float mb0[8];
    float mW1[8][8]; float mb1[8];
    float mW2[4][8]; float mb2[4];
    float pW1[2][8][2]; float pb1[2][8];
    float pW2[2][8][8]; float pb2[2][8];
    float pW3[2][8];    float pb3[2];
};

__constant__ Params cP;       // read via LDCU -> UR operands in FFMA
__device__ Params g_stage;    // staging buffer written by pack_kernel

__global__ void pack_kernel(const float* mW0, const float* mb0, const float* mW1,
                            const float* mb1, const float* mW2, const float* mb2,
                            const float* pW1, const float* pb1, const float* pW2,
                            const float* pb2, const float* pW3, const float* pb3)
{
    const float* srcs[12] = {mW0, mb0, mW1, mb1, mW2, mb2,
                             pW1, pb1, pW2, pb2, pW3, pb3};
    const int lens[12] = {16, 8, 64, 8, 32, 4, 32, 16, 128, 16, 16, 2};
    float* dst = (float*)&g_stage;
    int off = 0;
    for (int k = 0; k < 12; k++) {
        for (int i = threadIdx.x; i < lens[k]; i += blockDim.x)
            dst[off + i] = srcs[k][i];
        off += lens[k];
    }
}

__device__ __forceinline__ float rcp_apx(float x) {
    float y; asm("rcp.approx.f32 %0, %1;" : "=f"(y) : "f"(x)); return y;
}
// Accurate tanh: (e^{2x}-1)/(e^{2x}+1) = 1 - 2/(e^{2x}+1). Robust at +-inf.
__device__ __forceinline__ float tanh_f(float x) {
    float e = __expf(2.0f * x);
    return fmaf(-2.0f, rcp_apx(e + 1.0f), 1.0f);
}
__device__ __forceinline__ float sigm_f(float x) {
    float e = __expf(-x);
    return rcp_apx(1.0f + e);
}
__device__ __forceinline__ float elu_f(float x) {
    return x > 0.0f ? x : (__expf(x) - 1.0f);
}

__global__ void __launch_bounds__(TPB, 2)
ode_kernel(const float* __restrict__ x, float* __restrict__ out, int npairs)
{
    int t = blockIdx.x * TPB + threadIdx.x;
    if (t >= npairs) return;

    // Two points per thread: one float4 = {x0_a, x1_a, x0_b, x1_b}
    float4 xv = ((const float4*)x)[t];
    float X0[2] = {xv.x, xv.z};
    float X1[2] = {xv.y, xv.w};
    float OUT0[2], OUT1[2];

#pragma unroll
    for (int u = 0; u < 2; u++) {
        float x0 = X0[u], x1 = X1[u];

        // ---------- m-net: 2 -> 8 -> 8 -> 4, ELU ----------
        float h[8];
#pragma unroll
        for (int o = 0; o < 8; o++)
            h[o] = elu_f(fmaf(cP.mW0[o][0], x0, fmaf(cP.mW0[o][1], x1, cP.mb0[o])));

        float h2[8];
#pragma unroll
        for (int q = 0; q < 8; q++) {
            float z = cP.mb1[q];
#pragma unroll
            for (int o = 0; o < 8; o++) z = fmaf(cP.mW1[q][o], h[o], z);
            h2[q] = elu_f(z);
        }

        float bm[4];
#pragma unroll
        for (int j = 0; j < 4; j++) {
            float z = cP.mb2[j];
#pragma unroll
            for (int o = 0; o < 8; o++) z = fmaf(cP.mW2[j][o], h2[o], z);
            bm[j] = z;
        }
        float m2    = fmaf(bm[0], bm[1], bm[2] * bm[3]);
        float mag00 = fmaf(bm[0], bm[0], bm[2] * bm[2]);
        float mag11 = fmaf(bm[1], bm[1], bm[3] * bm[3]);

        // ---------- p-net ensemble (NV=2): forward + analytic grad wrt x ----------
        float gi0 = 0.0f, gi1 = 0.0f;
#pragma unroll
        for (int v = 0; v < 2; v++) {
            float f1[8];
#pragma unroll
            for (int p = 0; p < 8; p++)
                f1[p] = tanh_f(fmaf(cP.pW1[v][p][0], x0,
                                fmaf(cP.pW1[v][p][1], x1, cP.pb1[v][p])));

            float f2[8];
#pragma unroll
            for (int q = 0; q < 8; q++) {
                float z = cP.pb2[v][q];
#pragma unroll
                for (int p = 0; p < 8; p++) z = fmaf(cP.pW2[v][q][p], f1[p], z);
                f2[q] = tanh_f(z);
            }

            float z3 = cP.pb3[v];
#pragma unroll
            for (int p = 0; p < 8; p++) z3 = fmaf(cP.pW3[v][p], f2[p], z3);

            float f3 = sigm_f(z3);     // reference applies sigmoid twice
            float s  = sigm_f(f3);
            float d  = s * (1.0f - s);

            float gq[8];
#pragma unroll
            for (int q = 0; q < 8; q++)
                gq[q] = d * cP.pW3[v][q] * (1.0f - f2[q] * f2[q]);

#pragma unroll
            for (int p = 0; p < 8; p++) {
                float acc = 0.0f;
#pragma unroll
                for (int q = 0; q < 8; q++) acc = fmaf(gq[q], cP.pW2[v][q][p], acc);
                acc *= (1.0f - f1[p] * f1[p]);
                gi0 = fmaf(acc, cP.pW1[v][p][0], gi0);
                gi1 = fmaf(acc, cP.pW1[v][p][1], gi1);
            }
        }
        float g0 = 0.5f * gi0, g1 = 0.5f * gi1;   // mean over NV=2

        OUT0[u] = fmaf(mag00, g0, m2 * g1);
        OUT1[u] = fmaf(m2, g0, mag11 * g1);
    }

    ((float4*)out)[t] = make_float4(OUT0[0], OUT1[0], OUT0[1], OUT1[1]);
}

extern "C" void kernel_launch(void* const* d_in, const int* in_sizes, int n_in,
                              void* d_out, int out_size)
{
    // Input order: t, x, mW0, mb0, mW1, mb1, mW2, mb2, pW1, pb1, pW2, pb2, pW3, pb3
    const float* x = (const float*)d_in[1];
    float* out = (float*)d_out;
    int B = in_sizes[1] / 2;

    pack_kernel<<<1, 128>>>((const float*)d_in[2],  (const float*)d_in[3],
                            (const float*)d_in[4],  (const float*)d_in[5],
                            (const float*)d_in[6],  (const float*)d_in[7],
                            (const float*)d_in[8],  (const float*)d_in[9],
                            (const float*)d_in[10], (const float*)d_in[11],
                            (const float*)d_in[12], (const float*)d_in[13]);

    void* stage_addr = nullptr;
    cudaGetSymbolAddress(&stage_addr, g_stage);
    cudaMemcpyToSymbolAsync(cP, stage_addr, sizeof(Params), 0,
                            cudaMemcpyDeviceToDevice, (cudaStream_t)0);

    int npairs = B / 2;
    int grid = (npairs + TPB - 1) / TPB;
    ode_kernel<<<grid, TPB>>>(x, out, npairs);
}

// round 2
// speedup vs baseline: 1.1871x; 1.1871x over previous
#include <cuda_runtime.h>

#define TPB 256
typedef unsigned long long ull;

// ---- flat constant layout (floats duplicated to {w,w} 64-bit pairs) ----
// mW0[8][2]@0  mb0[8]@16  mW1[8][8]@24  mb1[8]@88  mW2[4][8]@96  mb2[4]@128
// pW1[2][8][2]@132  pb1[2][8]@164  pW2[2][8][8]@180  pb2[2][8]@308
// pW3[2][8]@324  pb3[2]@340   total 342
#define OFF_mW0 0
#define OFF_mb0 16
#define OFF_mW1 24
#define OFF_mb1 88
#define OFF_mW2 96
#define OFF_mb2 128
#define OFF_pW1 132
#define OFF_pb1 164
#define OFF_pW2 180
#define OFF_pb2 308
#define OFF_pW3 324
#define OFF_pb3 340
#define NPARAM 342

__constant__ ull cW[NPARAM];
__device__ ull g_stage[NPARAM];

__global__ void pack_kernel(const float* mW0, const float* mb0, const float* mW1,
                            const float* mb1, const float* mW2, const float* mb2,
                            const float* pW1, const float* pb1, const float* pW2,
                            const float* pb2, const float* pW3, const float* pb3)
{
    const float* srcs[12] = {mW0, mb0, mW1, mb1, mW2, mb2,
                             pW1, pb1, pW2, pb2, pW3, pb3};
    const int lens[12] = {16, 8, 64, 8, 32, 4, 32, 16, 128, 16, 16, 2};
    int off = 0;
    for (int k = 0; k < 12; k++) {
        for (int i = threadIdx.x; i < lens[k]; i += blockDim.x) {
            unsigned u = __float_as_uint(srcs[k][i]);
            g_stage[off + i] = (ull)u | ((ull)u << 32);
        }
        off += lens[k];
    }
}

// ---- packed f32x2 primitives ----
__device__ __forceinline__ ull f2pk(float lo, float hi) {
    ull r; asm("mov.b64 %0,{%1,%2};" : "=l"(r) : "f"(lo), "f"(hi)); return r;
}
__device__ __forceinline__ void f2up(ull v, float& lo, float& hi) {
    asm("mov.b64 {%0,%1},%2;" : "=f"(lo), "=f"(hi) : "l"(v));
}
__device__ __forceinline__ ull ffma2(ull a, ull b, ull c) {
    ull d; asm("fma.rn.f32x2 %0,%1,%2,%3;" : "=l"(d) : "l"(a), "l"(b), "l"(c)); return d;
}
__device__ __forceinline__ ull fmul2(ull a, ull b) {
    ull d; asm("mul.rn.f32x2 %0,%1,%2;" : "=l"(d) : "l"(a), "l"(b)); return d;
}

// packed constants (both halves identical fp32 bit patterns)
#define C_MONE  0xBF800000BF800000ULL   // {-1,-1}
#define C_MTWO  0xC0000000C0000000ULL   // {-2,-2}
#define C_ONE   0x3F8000003F800000ULL   // {1,1}
#define C_HALF  0x3F0000003F000000ULL   // {0.5,0.5}
#define C_2L2E  0x4038AA3B4038AA3BULL   // {2*log2(e)} = 2.8853900818f

__device__ __forceinline__ float rcp_apx(float x) {
    float y; asm("rcp.approx.f32 %0, %1;" : "=f"(y) : "f"(x)); return y;
}
__device__ __forceinline__ float ex2_apx(float x) {
    float y; asm("ex2.approx.f32 %0, %1;" : "=f"(y) : "f"(x)); return y;
}
__device__ __forceinline__ float sigm_f(float x) {
    return rcp_apx(1.0f + __expf(-x));
}
// packed tanh: 1 - 2/(exp(2x)+1); exp via ex2(2*log2e*x)
__device__ __forceinline__ ull tanh2(ull z) {
    ull a = fmul2(z, C_2L2E);
    float lo, hi; f2up(a, lo, hi);
    float rlo = rcp_apx(ex2_apx(lo) + 1.0f);
    float rhi = rcp_apx(ex2_apx(hi) + 1.0f);
    return ffma2(C_MTWO, f2pk(rlo, rhi), C_ONE);
}
// packed ELU: scalar select per half
__device__ __forceinline__ ull elu2(ull z) {
    float lo, hi; f2up(z, lo, hi);
    lo = lo > 0.0f ? lo : (__expf(lo) - 1.0f);
    hi = hi > 0.0f ? hi : (__expf(hi) - 1.0f);
    return f2pk(lo, hi);
}
// d = s*(1-s), s = sigmoid(sigmoid(z))  (reference applies sigmoid twice)
__device__ __forceinline__ float dsig(float z) {
    float s = sigm_f(sigm_f(z));
    return s * (1.0f - s);
}

__global__ void __launch_bounds__(TPB, 2)
ode_kernel(const float* __restrict__ x, float* __restrict__ out, int npairs)
{
    int t = blockIdx.x * TPB + threadIdx.x;
    if (t >= npairs) return;

    float4 xv = ((const float4*)x)[t];
    ull X0 = f2pk(xv.x, xv.z);   // lo = point a, hi = point b
    ull X1 = f2pk(xv.y, xv.w);

    // ---------- m-net: 2 -> 8 -> 8 -> 4 (ELU) ----------
    ull h[8];
#pragma unroll
    for (int o = 0; o < 8; o++) {
        ull z = ffma2(cW[OFF_mW0 + 2*o], X0,
                 ffma2(cW[OFF_mW0 + 2*o + 1], X1, cW[OFF_mb0 + o]));
        h[o] = elu2(z);
    }
    ull h2[8];
#pragma unroll
    for (int q = 0; q < 8; q++) {
        ull z = cW[OFF_mb1 + q];
#pragma unroll
        for (int o = 0; o < 8; o++) z = ffma2(cW[OFF_mW1 + q*8 + o], h[o], z);
        h2[q] = elu2(z);
    }
    ull bm[4];
#pragma unroll
    for (int j = 0; j < 4; j++) {
        ull z = cW[OFF_mb2 + j];
#pragma unroll
        for (int o = 0; o < 8; o++) z = ffma2(cW[OFF_mW2 + j*8 + o], h2[o], z);
        bm[j] = z;
    }
    ull m2    = ffma2(bm[0], bm[1], fmul2(bm[2], bm[3]));
    ull mag00 = ffma2(bm[0], bm[0], fmul2(bm[2], bm[2]));
    ull mag11 = ffma2(bm[1], bm[1], fmul2(bm[3], bm[3]));

    // ---------- p-net ensemble (NV=2): forward + analytic input-grad ----------
    ull gi0 = 0ULL, gi1 = 0ULL;
#pragma unroll
    for (int v = 0; v < 2; v++) {
        ull f1[8];
#pragma unroll
        for (int p = 0; p < 8; p++) {
            ull z = ffma2(cW[OFF_pW1 + v*16 + 2*p], X0,
                     ffma2(cW[OFF_pW1 + v*16 + 2*p + 1], X1, cW[OFF_pb1 + v*8 + p]));
            f1[p] = tanh2(z);
        }
        ull f2v[8];
#pragma unroll
        for (int q = 0; q < 8; q++) {
            ull z = cW[OFF_pb2 + v*8 + q];
#pragma unroll
            for (int p = 0; p < 8; p++)
                z = ffma2(cW[OFF_pW2 + v*64 + q*8 + p], f1[p], z);
            f2v[q] = tanh2(z);
        }
        ull z3 = cW[OFF_pb3 + v];
#pragma unroll
        for (int p = 0; p < 8; p++)
            z3 = ffma2(cW[OFF_pW3 + v*8 + p], f2v[p], z3);

        float zlo, zhi; f2up(z3, zlo, zhi);
        ull d2 = f2pk(dsig(zlo), dsig(zhi));

        // gq' = d * W3 * (f2^2 - 1)   [negated; sign cancels with (f1^2 - 1) below]
        ull gq[8];
#pragma unroll
        for (int q = 0; q < 8; q++) {
            ull fm1 = ffma2(f2v[q], f2v[q], C_MONE);
            gq[q] = fmul2(fmul2(d2, cW[OFF_pW3 + v*8 + q]), fm1);
        }
#pragma unroll
        for (int p = 0; p < 8; p++) {
            ull acc = 0ULL;
#pragma unroll
            for (int q = 0; q < 8; q++)
                acc = ffma2(gq[q], cW[OFF_pW2 + v*64 + q*8 + p], acc);
            ull fm1 = ffma2(f1[p], f1[p], C_MONE);   // (f1^2 - 1): second negation cancels
            acc = fmul2(acc, fm1);
            gi0 = ffma2(acc, cW[OFF_pW1 + v*16 + 2*p], gi0);
            gi1 = ffma2(acc, cW[OFF_pW1 + v*16 + 2*p + 1], gi1);
        }
    }
    ull g0 = fmul2(gi0, C_HALF);   // mean over NV=2
    ull g1 = fmul2(gi1, C_HALF);

    ull O0 = ffma2(mag00, g0, fmul2(m2, g1));
    ull O1 = ffma2(m2, g0, fmul2(mag11, g1));

    float oa, ob, oc, od;
    f2up(O0, oa, ob);
    f2up(O1, oc, od);
    ((float4*)out)[t] = make_float4(oa, oc, ob, od);
}

extern "C" void kernel_launch(void* const* d_in, const int* in_sizes, int n_in,
                              void* d_out, int out_size)
{
    // Input order: t, x, mW0, mb0, mW1, mb1, mW2, mb2, pW1, pb1, pW2, pb2, pW3, pb3
    const float* x = (const float*)d_in[1];
    float* out = (float*)d_out;
    int B = in_sizes[1] / 2;

    pack_kernel<<<1, 128>>>((const float*)d_in[2],  (const float*)d_in[3],
                            (const float*)d_in[4],  (const float*)d_in[5],
                            (const float*)d_in[6],  (const float*)d_in[7],
                            (const float*)d_in[8],  (const float*)d_in[9],
                            (const float*)d_in[10], (const float*)d_in[11],
                            (const float*)d_in[12], (const float*)d_in[13]);

    void* stage_addr = nullptr;
    cudaGetSymbolAddress(&stage_addr, g_stage);
    cudaMemcpyToSymbolAsync(cW, stage_addr, sizeof(ull) * NPARAM, 0,
                            cudaMemcpyDeviceToDevice, (cudaStream_t)0);

    int npairs = B / 2;
    int grid = (npairs + TPB - 1) / TPB;
    ode_kernel<<<grid, TPB>>>(x, out, npairs);
}

// round 3
// speedup vs baseline: 1.4651x; 1.2342x over previous
#include <cuda_runtime.h>

#define TPB 256
typedef unsigned long long ull;

// ---- flat constant layout (floats duplicated to {w,w} 64-bit pairs) ----
#define OFF_mW0 0
#define OFF_mb0 16
#define OFF_mW1 24
#define OFF_mb1 88
#define OFF_mW2 96
#define OFF_mb2 128
#define OFF_pW1 132
#define OFF_pb1 164
#define OFF_pW2 180
#define OFF_pb2 308
#define OFF_pW3 324
#define OFF_pb3 340
#define NPARAM 342

__constant__ ull cW[NPARAM];
__device__ ull g_stage[NPARAM];

__global__ void pack_kernel(const float* mW0, const float* mb0, const float* mW1,
                            const float* mb1, const float* mW2, const float* mb2,
                            const float* pW1, const float* pb1, const float* pW2,
                            const float* pb2, const float* pW3, const float* pb3)
{
    const float* srcs[12] = {mW0, mb0, mW1, mb1, mW2, mb2,
                             pW1, pb1, pW2, pb2, pW3, pb3};
    const int lens[12] = {16, 8, 64, 8, 32, 4, 32, 16, 128, 16, 16, 2};
    int off = 0;
    for (int k = 0; k < 12; k++) {
        for (int i = threadIdx.x; i < lens[k]; i += blockDim.x) {
            unsigned u = __float_as_uint(srcs[k][i]);
            g_stage[off + i] = (ull)u | ((ull)u << 32);
        }
        off += lens[k];
    }
}

// ---- packed f32x2 primitives ----
__device__ __forceinline__ ull f2pk(float lo, float hi) {
    ull r; asm("mov.b64 %0,{%1,%2};" : "=l"(r) : "f"(lo), "f"(hi)); return r;
}
__device__ __forceinline__ void f2up(ull v, float& lo, float& hi) {
    asm("mov.b64 {%0,%1},%2;" : "=f"(lo), "=f"(hi) : "l"(v));
}
__device__ __forceinline__ ull ffma2(ull a, ull b, ull c) {
    ull d; asm("fma.rn.f32x2 %0,%1,%2,%3;" : "=l"(d) : "l"(a), "l"(b), "l"(c)); return d;
}
__device__ __forceinline__ ull fmul2(ull a, ull b) {
    ull d; asm("mul.rn.f32x2 %0,%1,%2;" : "=l"(d) : "l"(a), "l"(b)); return d;
}

#define C_MONE  0xBF800000BF800000ULL   // {-1,-1}
#define C_HALF  0x3F0000003F000000ULL   // {0.5,0.5}

__device__ __forceinline__ float ex2_apx(float x) {
    float y; asm("ex2.approx.f32 %0, %1;" : "=f"(y) : "f"(x)); return y;
}
__device__ __forceinline__ float tanh_apx(float x) {
    float y; asm("tanh.approx.f32 %0, %1;" : "=f"(y) : "f"(x)); return y;
}
// packed tanh: two MUFU.TANH, no algebra
__device__ __forceinline__ ull tanh2(ull z) {
    float lo, hi; f2up(z, lo, hi);
    return f2pk(tanh_apx(lo), tanh_apx(hi));
}
// sigmoid via tanh: 0.5*tanh(0.5x) + 0.5
__device__ __forceinline__ float sigm_f(float x) {
    return fmaf(0.5f, tanh_apx(0.5f * x), 0.5f);
}
// packed ELU
__device__ __forceinline__ ull elu2(ull z) {
    const float L2E = 1.4426950408889634f;
    float lo, hi; f2up(z, lo, hi);
    float elo = ex2_apx(lo * L2E) - 1.0f;
    float ehi = ex2_apx(hi * L2E) - 1.0f;
    lo = lo > 0.0f ? lo : elo;
    hi = hi > 0.0f ? hi : ehi;
    return f2pk(lo, hi);
}
// d = s*(1-s), s = sigmoid(sigmoid(z))  (reference applies sigmoid twice)
__device__ __forceinline__ float dsig(float z) {
    float s = sigm_f(sigm_f(z));
    return fmaf(-s, s, s);
}

__global__ void __launch_bounds__(TPB, 2)
ode_kernel(const float* __restrict__ x, float* __restrict__ out, int npairs)
{
    int t = blockIdx.x * TPB + threadIdx.x;
    if (t >= npairs) return;

    float4 xv = ((const float4*)x)[t];
    ull X0 = f2pk(xv.x, xv.z);   // lo = point a, hi = point b
    ull X1 = f2pk(xv.y, xv.w);

    // ---------- m-net: 2 -> 8 -> 8 -> 4 (ELU) ----------
    ull h[8];
#pragma unroll
    for (int o = 0; o < 8; o++) {
        ull z = ffma2(cW[OFF_mW0 + 2*o], X0,
                 ffma2(cW[OFF_mW0 + 2*o + 1], X1, cW[OFF_mb0 + o]));
        h[o] = elu2(z);
    }
    ull h2[8];
#pragma unroll
    for (int q = 0; q < 8; q++) {
        ull z = cW[OFF_mb1 + q];
#pragma unroll
        for (int o = 0; o < 8; o++) z = ffma2(cW[OFF_mW1 + q*8 + o], h[o], z);
        h2[q] = elu2(z);
    }
    ull bm[4];
#pragma unroll
    for (int j = 0; j < 4; j++) {
        ull z = cW[OFF_mb2 + j];
#pragma unroll
        for (int o = 0; o < 8; o++) z = ffma2(cW[OFF_mW2 + j*8 + o], h2[o], z);
        bm[j] = z;
    }
    ull m2    = ffma2(bm[0], bm[1], fmul2(bm[2], bm[3]));
    ull mag00 = ffma2(bm[0], bm[0], fmul2(bm[2], bm[2]));
    ull mag11 = ffma2(bm[1], bm[1], fmul2(bm[3], bm[3]));

    // ---------- p-net ensemble (NV=2): forward + analytic input-grad ----------
    ull gi0 = 0ULL, gi1 = 0ULL;
#pragma unroll
    for (int v = 0; v < 2; v++) {
        ull f1[8];
#pragma unroll
        for (int p = 0; p < 8; p++) {
            ull z = ffma2(cW[OFF_pW1 + v*16 + 2*p], X0,
                     ffma2(cW[OFF_pW1 + v*16 + 2*p + 1], X1, cW[OFF_pb1 + v*8 + p]));
            f1[p] = tanh2(z);
        }
        ull f2v[8];
#pragma unroll
        for (int q = 0; q < 8; q++) {
            ull z = cW[OFF_pb2 + v*8 + q];
#pragma unroll
            for (int p = 0; p < 8; p++)
                z = ffma2(cW[OFF_pW2 + v*64 + q*8 + p], f1[p], z);
            f2v[q] = tanh2(z);
        }
        ull z3 = cW[OFF_pb3 + v];
#pragma unroll
        for (int p = 0; p < 8; p++)
            z3 = ffma2(cW[OFF_pW3 + v*8 + p], f2v[p], z3);

        float zlo, zhi; f2up(z3, zlo, zhi);
        ull d2 = f2pk(dsig(zlo), dsig(zhi));

        // gq' = d * W3 * (f2^2 - 1)   [negated; sign cancels with (f1^2 - 1) below]
        ull gq[8];
#pragma unroll
        for (int q = 0; q < 8; q++) {
            ull fm1 = ffma2(f2v[q], f2v[q], C_MONE);
            gq[q] = fmul2(fmul2(d2, cW[OFF_pW3 + v*8 + q]), fm1);
        }
#pragma unroll
        for (int p = 0; p < 8; p++) {
            ull acc = 0ULL;
#pragma unroll
            for (int q = 0; q < 8; q++)
                acc = ffma2(gq[q], cW[OFF_pW2 + v*64 + q*8 + p], acc);
            ull fm1 = ffma2(f1[p], f1[p], C_MONE);   // (f1^2 - 1): second negation cancels
            acc = fmul2(acc, fm1);
            gi0 = ffma2(acc, cW[OFF_pW1 + v*16 + 2*p], gi0);
            gi1 = ffma2(acc, cW[OFF_pW1 + v*16 + 2*p + 1], gi1);
        }
    }
    ull g0 = fmul2(gi0, C_HALF);   // mean over NV=2
    ull g1 = fmul2(gi1, C_HALF);

    ull O0 = ffma2(mag00, g0, fmul2(m2, g1));
    ull O1 = ffma2(m2, g0, fmul2(mag11, g1));

    float oa, ob, oc, od;
    f2up(O0, oa, ob);
    f2up(O1, oc, od);
    ((float4*)out)[t] = make_float4(oa, oc, ob, od);
}

extern "C" void kernel_launch(void* const* d_in, const int* in_sizes, int n_in,
                              void* d_out, int out_size)
{
    // Input order: t, x, mW0, mb0, mW1, mb1, mW2, mb2, pW1, pb1, pW2, pb2, pW3, pb3
    const float* x = (const float*)d_in[1];
    float* out = (float*)d_out;
    int B = in_sizes[1] / 2;

    pack_kernel<<<1, 128>>>((const float*)d_in[2],  (const float*)d_in[3],
                            (const float*)d_in[4],  (const float*)d_in[5],
                            (const float*)d_in[6],  (const float*)d_in[7],
                            (const float*)d_in[8],  (const float*)d_in[9],
                            (const float*)d_in[10], (const float*)d_in[11],
                            (const float*)d_in[12], (const float*)d_in[13]);

    void* stage_addr = nullptr;
    cudaGetSymbolAddress(&stage_addr, g_stage);
    cudaMemcpyToSymbolAsync(cW, stage_addr, sizeof(ull) * NPARAM, 0,
                            cudaMemcpyDeviceToDevice, (cudaStream_t)0);

    int npairs = B / 2;
    int grid = (npairs + TPB - 1) / TPB;
    ode_kernel<<<grid, TPB>>>(x, out, npairs);
}